// round 13
// baseline (speedup 1.0000x reference)
#include <cuda_runtime.h>
#include <math.h>

// Problem constants (fixed by the reference).
#define DD   128
#define HH   8
#define BB   8
#define SS   4096
#define EPSF 1e-8f
#define TBA  8            // tokens per anchor task
#define TBD  8            // tokens per delta task
#define RS2  258          // packed-R row stride in floats: row i at Rs[i*258 + 2j] = (r,r)
#define XST  12           // xs row stride (floats): 48B rows, 16B-aligned for LDS.128
#define NTHREAD 448       // 14 warps/SM
#define NWARP   14
#define NBLOCK  148

// SMEM floats: packed R (128*258 = 33024) + per-warp xs (128*12)
#define SMEM_FLOATS (128*RS2 + NWARP*128*XST)   // 33024 + 21504 = 54528 -> 218112 B

// Work-stealing counters; zeroed by cudaMemsetAsync before each replay.
__device__ unsigned int g_ctr[2];

// ---------------- Blackwell packed-fp32 helpers ----------------
__device__ __forceinline__ void fma2(unsigned long long& d, unsigned long long a, unsigned long long b) {
    asm("fma.rn.f32x2 %0, %1, %2, %0;" : "+l"(d) : "l"(a), "l"(b));
}
__device__ __forceinline__ float2 unpack2(unsigned long long p) {
    unsigned int lo, hi;
    asm("mov.b64 {%0, %1}, %2;" : "=r"(lo), "=r"(hi) : "l"(p));
    return make_float2(__uint_as_float(lo), __uint_as_float(hi));
}
__device__ __forceinline__ float warp_sum(float v) {
#pragma unroll
    for (int o = 16; o; o >>= 1) v += __shfl_xor_sync(0xffffffffu, v, o);
    return v;
}
__device__ __forceinline__ unsigned int next_task(int which, int lane) {
    unsigned int t;
    if (lane == 0) t = atomicAdd(&g_ctr[which], 1u);
    return __shfl_sync(0xffffffffu, t, 0);
}

// 128-long matvec, 8 tokens, packed-R operands (no MOVs, no scalar R loads).
// RSTEP (in floats): 2   -> row walk   (matvec1: base = Rs + i*RS2,   step 2 per j)
//                    RS2 -> column walk (matvec2: base = Rs + 2*j_out, step RS2 per i)
// acc[k*4+p] = packed (token 2p, 2p+1) for the lane's k-th output element.
template <int RSTEP>
__device__ __forceinline__ void matvec8p(const float* __restrict__ r0, const float* __restrict__ r1,
                                         const float* __restrict__ r2, const float* __restrict__ r3,
                                         const float* __restrict__ xs, unsigned long long acc[16]) {
#pragma unroll
    for (int p = 0; p < 16; p++) acc[p] = 0ull;
#pragma unroll 8
    for (int j = 0; j < 128; j++) {
        unsigned long long rr0 = *(const unsigned long long*)(r0 + j * RSTEP);  // LDS.64 (r,r)
        unsigned long long rr1 = *(const unsigned long long*)(r1 + j * RSTEP);
        unsigned long long rr2 = *(const unsigned long long*)(r2 + j * RSTEP);
        unsigned long long rr3 = *(const unsigned long long*)(r3 + j * RSTEP);
        ulonglong2 pa = *(const ulonglong2*)(xs + j * XST);      // tokens 0..3 (broadcast)
        ulonglong2 pb = *(const ulonglong2*)(xs + j * XST + 4);  // tokens 4..7
        fma2(acc[0],  rr0, pa.x); fma2(acc[1],  rr0, pa.y); fma2(acc[2],  rr0, pb.x); fma2(acc[3],  rr0, pb.y);
        fma2(acc[4],  rr1, pa.x); fma2(acc[5],  rr1, pa.y); fma2(acc[6],  rr1, pb.x); fma2(acc[7],  rr1, pb.y);
        fma2(acc[8],  rr2, pa.x); fma2(acc[9],  rr2, pa.y); fma2(acc[10], rr2, pb.x); fma2(acc[11], rr2, pb.y);
        fma2(acc[12], rr3, pa.x); fma2(acc[13], rr3, pa.y); fma2(acc[14], rr3, pb.x); fma2(acc[15], rr3, pb.y);
    }
}

// Stage R as duplicated pairs: Rs[i*RS2 + 2j] = Rs[i*RS2 + 2j + 1] = R[i*128+j].
__device__ __forceinline__ void stage_Rdup(float* Rs, const float* __restrict__ R, int tid) {
#pragma unroll 4
    for (int idx = tid; idx < 128 * 128; idx += NTHREAD) {
        int i = idx >> 7, j = idx & 127;
        float v = R[idx];
        *(float2*)(Rs + i * RS2 + 2 * j) = make_float2(v, v);   // STS.64
    }
}

// ---------------- Phase 1: anchor head (ResidualQuant), TB=8 ----------------
__global__ void __launch_bounds__(NTHREAD, 1)
anchor_kernel(const float* __restrict__ kv, const float* __restrict__ Ra,
              const float* __restrict__ cba, float* __restrict__ out, int ntask) {
    extern __shared__ float sm[];
    float* Rs = sm;
    const int tid = threadIdx.x;
    const int w = tid >> 5, L = tid & 31;
    float* xs = sm + 128 * RS2 + w * (128 * XST);

    stage_Rdup(Rs, Ra, tid);
    const float c0 = cba[0], c1 = cba[1], c2 = cba[2], c3 = cba[3];
    const float t0 = 0.5f * (c0 + c1), t1 = 0.5f * (c1 + c2), t2 = 0.5f * (c2 + c3);
    __syncthreads();

    // matvec1 row bases (walk j, step 2); matvec2 column bases (walk i, step RS2)
    const float* rr0 = Rs + (L +  0) * RS2;
    const float* rr1 = Rs + (L + 32) * RS2;
    const float* rr2 = Rs + (L + 64) * RS2;
    const float* rr3 = Rs + (L + 96) * RS2;
    const float* rc0 = Rs + 2 * (L +  0);
    const float* rc1 = Rs + 2 * (L + 32);
    const float* rc2 = Rs + 2 * (L + 64);
    const float* rc3 = Rs + 2 * (L + 96);

    for (;;) {
        unsigned int task = next_task(0, L);
        if (task >= (unsigned)ntask) break;
        const int b = (int)(task >> 9);                 // 512 chunks per b
        const int sbase = ((int)task & 511) * TBA;
        const unsigned int base = ((unsigned)(b * HH) * SS + (unsigned)sbase) * DD;

        // ---- stage x (coalesced LDG.32, 4-way STS), batched reductions ----
        float sq[TBA], nn[TBA], inv[TBA];
#pragma unroll
        for (int t = 0; t < TBA; t++) {
            float ssq = 0.f;
#pragma unroll
            for (int c = 0; c < 4; c++) {
                int j = L + 32 * c;
                float x = kv[base + t * DD + j];
                xs[j * XST + t] = x;
                ssq += x * x;
            }
            sq[t] = ssq;
        }
#pragma unroll
        for (int t = 0; t < TBA; t++) {
            float tot = warp_sum(sq[t]);
            nn[t] = sqrtf(tot);
            inv[t] = 1.0f / (nn[t] + EPSF);
        }
        __syncwarp();

        unsigned long long acc[16];
        matvec8p<2>(rr0, rr1, rr2, rr3, xs, acc);

        // ---- pass A: quantize + |res| accumulation ----
        float A[TBA];
#pragma unroll
        for (int t = 0; t < TBA; t++) A[t] = 0.f;
#pragma unroll
        for (int k = 0; k < 4; k++) {
#pragma unroll
            for (int p = 0; p < 4; p++) {
                float2 y = unpack2(acc[k * 4 + p]);
                float y0 = y.x * inv[2 * p], y1 = y.y * inv[2 * p + 1];
                float q0 = (y0 <= t1) ? ((y0 <= t0) ? c0 : c1) : ((y0 <= t2) ? c2 : c3);
                float q1 = (y1 <= t1) ? ((y1 <= t0) ? c0 : c1) : ((y1 <= t2) ? c2 : c3);
                A[2 * p]     += fabsf(y0 - q0);
                A[2 * p + 1] += fabsf(y1 - q1);
            }
        }
#pragma unroll
        for (int t = 0; t < TBA; t++) A[t] = warp_sum(A[t]) * (1.0f / 128.0f);  // alpha

        __syncwarp();   // matvec1 done reading xs warp-wide

        // ---- pass B: yhat -> xs ----
#pragma unroll
        for (int k = 0; k < 4; k++) {
            int i = L + 32 * k;
#pragma unroll
            for (int p = 0; p < 4; p++) {
                float2 y = unpack2(acc[k * 4 + p]);
#pragma unroll
                for (int h = 0; h < 2; h++) {
                    int t = 2 * p + h;
                    float yy = (h ? y.y : y.x) * inv[t];
                    float q = (yy <= t1) ? ((yy <= t0) ? c0 : c1) : ((yy <= t2) ? c2 : c3);
                    float res = yy - q;
                    float sg = (res > 0.f) ? 1.f : ((res < 0.f) ? -1.f : 0.f);
                    xs[i * XST + t] = q + A[t] * sg;
                }
            }
        }
        __syncwarp();

        matvec8p<RS2>(rc0, rc1, rc2, rc3, xs, acc);

        // ---- output: out = rec * norm ----
#pragma unroll
        for (int t = 0; t < TBA; t++) {
            int p = t >> 1;
#pragma unroll
            for (int k = 0; k < 4; k++) {
                float2 r = unpack2(acc[k * 4 + p]);
                float rv = (t & 1) ? r.y : r.x;
                out[base + t * DD + L + 32 * k] = rv * nn[t];
            }
        }
        __syncwarp();   // protect xs before next task
    }
}

// ---------------- Phase 2: delta heads (PolarQuant), TB=8, work-stealing ----------------
__global__ void __launch_bounds__(NTHREAD, 1)
delta_kernel(const float* __restrict__ kv, const float* __restrict__ Rd,
             const float* __restrict__ cbd, const float* __restrict__ anc,
             float* __restrict__ out, int ntask) {
    extern __shared__ float sm[];
    float* Rs = sm;
    const int tid = threadIdx.x;
    const int w = tid >> 5, L = tid & 31;
    float* xs = sm + 128 * RS2 + w * (128 * XST);

    stage_Rdup(Rs, Rd, tid);
    const float c0 = cbd[0], c1 = cbd[1];
    const float mid = 0.5f * (c0 + c1);
    __syncthreads();

    const float* rr0 = Rs + (L +  0) * RS2;
    const float* rr1 = Rs + (L + 32) * RS2;
    const float* rr2 = Rs + (L + 64) * RS2;
    const float* rr3 = Rs + (L + 96) * RS2;
    const float* rc0 = Rs + 2 * (L +  0);
    const float* rc1 = Rs + 2 * (L + 32);
    const float* rc2 = Rs + 2 * (L + 64);
    const float* rc3 = Rs + 2 * (L + 96);

    for (;;) {
        unsigned int task = next_task(1, L);
        if (task >= (unsigned)ntask) break;
        // head-minor: consecutive tasks = same chunk, different head (anchor chunk L2 reuse)
        const int chunk = (int)(task / 7);
        const int h = (int)(task - chunk * 7) + 1;
        const int b = chunk >> 9;                       // 512 chunks per b
        const int sbase = (chunk & 511) * TBD;
        const unsigned int kbase = ((unsigned)(b * HH + h) * SS + (unsigned)sbase) * DD;
        const unsigned int abase = ((unsigned)(b * HH) * SS + (unsigned)sbase) * DD;

        // ---- stage delta = kv - anchor (coalesced), batched reductions ----
        float sq[TBD], nn[TBD], inv[TBD];
#pragma unroll
        for (int t = 0; t < TBD; t++) {
            float ssq = 0.f;
#pragma unroll
            for (int c = 0; c < 4; c++) {
                int j = L + 32 * c;
                float x = kv[kbase + t * DD + j] - anc[abase + t * DD + j];
                xs[j * XST + t] = x;
                ssq += x * x;
            }
            sq[t] = ssq;
        }
#pragma unroll
        for (int t = 0; t < TBD; t++) {
            float tot = warp_sum(sq[t]);
            nn[t] = sqrtf(tot);
            inv[t] = 1.0f / (nn[t] + EPSF);
        }
        __syncwarp();

        unsigned long long acc[16];
        matvec8p<2>(rr0, rr1, rr2, rr3, xs, acc);

        __syncwarp();   // all lanes done reading xs

        // ---- 1-bit polar quantize -> xs ----
#pragma unroll
        for (int k = 0; k < 4; k++) {
            int i = L + 32 * k;
#pragma unroll
            for (int p = 0; p < 4; p++) {
                float2 y = unpack2(acc[k * 4 + p]);
                float y0 = y.x * inv[2 * p], y1 = y.y * inv[2 * p + 1];
                xs[i * XST + 2 * p]     = (y0 <= mid) ? c0 : c1;
                xs[i * XST + 2 * p + 1] = (y1 <= mid) ? c0 : c1;
            }
        }
        __syncwarp();

        matvec8p<RS2>(rc0, rc1, rc2, rc3, xs, acc);

        // ---- output: out = anchor + rec * norm (anchor reload: L1/L2 hit) ----
#pragma unroll
        for (int t = 0; t < TBD; t++) {
            int p = t >> 1;
#pragma unroll
            for (int k = 0; k < 4; k++) {
                float2 r = unpack2(acc[k * 4 + p]);
                float rv = (t & 1) ? r.y : r.x;
                int j = L + 32 * k;
                out[kbase + t * DD + j] = anc[abase + t * DD + j] + rv * nn[t];
            }
        }
        __syncwarp();
    }
}

extern "C" void kernel_launch(void* const* d_in, const int* in_sizes, int n_in,
                              void* d_out, int out_size) {
    const float* kv  = (const float*)d_in[0];
    const float* Ra  = (const float*)d_in[1];
    const float* cba = (const float*)d_in[2];
    const float* Rd  = (const float*)d_in[3];
    const float* cbd = (const float*)d_in[4];
    float* out = (float*)d_out;

    const int smem_bytes = SMEM_FLOATS * (int)sizeof(float);  // 218112
    cudaFuncSetAttribute(anchor_kernel, cudaFuncAttributeMaxDynamicSharedMemorySize, smem_bytes);
    cudaFuncSetAttribute(delta_kernel,  cudaFuncAttributeMaxDynamicSharedMemorySize, smem_bytes);

    // Reset work-stealing counters via a memset node (graph-capturable).
    static void* ctr_addr = nullptr;
    if (!ctr_addr) cudaGetSymbolAddress(&ctr_addr, g_ctr);
    cudaMemsetAsync(ctr_addr, 0, 2 * sizeof(unsigned int));

    const int n_anchor_task = (BB * SS) / TBA;            // 4096
    const int n_delta_task  = (BB * SS) / TBD * 7;        // 28672

    anchor_kernel<<<NBLOCK, NTHREAD, smem_bytes>>>(kv, Ra, cba, out, n_anchor_task);
    delta_kernel <<<NBLOCK, NTHREAD, smem_bytes>>>(kv, Rd, cbd, out, out, n_delta_task);
}

// round 15
// speedup vs baseline: 1.1119x; 1.1119x over previous
#include <cuda_runtime.h>
#include <math.h>

// Problem constants (fixed by the reference).
#define DD   128
#define HH   8
#define BB   8
#define SS   4096
#define EPSF 1e-8f
#define TBA  8            // tokens per anchor task
#define TBD  16           // tokens per delta task
#define RSTRIDE 129       // padded R row stride: conflict-free row & column scalar reads
#define XSA  12           // anchor xs row stride (16B-aligned rows)
#define XSD  20           // delta xs row stride (16B-aligned rows)
#define NTHREAD 384       // 12 warps/SM, ~170-reg budget
#define NWARP   12
#define NBLOCK  148

// Per-warp smem floats: delta = xs(128*20) + stash(32); anchor = xs(128*12)
#define WFD (128*XSD + 32)
#define WFA (128*XSA)
#define SMEM_FLOATS_A (128*RSTRIDE + NWARP*WFA)   // 34944  -> 139776 B
#define SMEM_FLOATS_D (128*RSTRIDE + NWARP*WFD)   // 47616  -> 190464 B

// Work-stealing counters; zeroed by cudaMemsetAsync before each replay.
__device__ unsigned int g_ctr[2];

// ---------------- Blackwell packed-fp32 helpers ----------------
__device__ __forceinline__ unsigned long long pack2(float x) {
    unsigned long long d; unsigned int u = __float_as_uint(x);
    asm("mov.b64 %0, {%1, %1};" : "=l"(d) : "r"(u));
    return d;
}
__device__ __forceinline__ void fma2(unsigned long long& d, unsigned long long a, unsigned long long b) {
    asm("fma.rn.f32x2 %0, %1, %2, %0;" : "+l"(d) : "l"(a), "l"(b));
}
__device__ __forceinline__ float2 unpack2(unsigned long long p) {
    unsigned int lo, hi;
    asm("mov.b64 {%0, %1}, %2;" : "=r"(lo), "=r"(hi) : "l"(p));
    return make_float2(__uint_as_float(lo), __uint_as_float(hi));
}
__device__ __forceinline__ float warp_sum(float v) {
#pragma unroll
    for (int o = 16; o; o >>= 1) v += __shfl_xor_sync(0xffffffffu, v, o);
    return v;
}
__device__ __forceinline__ unsigned int next_task(int which, int lane) {
    unsigned int t;
    if (lane == 0) t = atomicAdd(&g_ctr[which], 1u);
    return __shfl_sync(0xffffffffu, t, 0);
}

// ---------------- software-pipelined matvecs ----------------
// Buffer load helpers (indices constant after unroll -> pure register arrays).

__device__ __forceinline__ void ld16(const float* r0, const float* r1, const float* r2, const float* r3,
                                     const float* xs, int j, int rstep,
                                     unsigned long long rr[4], ulonglong2 px[4]) {
    rr[0] = pack2(r0[j * rstep]);
    rr[1] = pack2(r1[j * rstep]);
    rr[2] = pack2(r2[j * rstep]);
    rr[3] = pack2(r3[j * rstep]);
    px[0] = *(const ulonglong2*)(xs + j * XSD);
    px[1] = *(const ulonglong2*)(xs + j * XSD + 4);
    px[2] = *(const ulonglong2*)(xs + j * XSD + 8);
    px[3] = *(const ulonglong2*)(xs + j * XSD + 12);
}
__device__ __forceinline__ void fb16(const unsigned long long rr[4], const ulonglong2 px[4],
                                     unsigned long long acc[32]) {
#pragma unroll
    for (int k = 0; k < 4; k++) {
        fma2(acc[k*8+0], rr[k], px[0].x); fma2(acc[k*8+1], rr[k], px[0].y);
        fma2(acc[k*8+2], rr[k], px[1].x); fma2(acc[k*8+3], rr[k], px[1].y);
        fma2(acc[k*8+4], rr[k], px[2].x); fma2(acc[k*8+5], rr[k], px[2].y);
        fma2(acc[k*8+6], rr[k], px[3].x); fma2(acc[k*8+7], rr[k], px[3].y);
    }
}

// TB=16 matvec, double-buffered: loads for j+1 issue before FMA block of j.
template <int RSTEP>
__device__ __forceinline__ void matvec16(const float* __restrict__ r0, const float* __restrict__ r1,
                                         const float* __restrict__ r2, const float* __restrict__ r3,
                                         const float* __restrict__ xs, unsigned long long acc[32]) {
#pragma unroll
    for (int p = 0; p < 32; p++) acc[p] = 0ull;
    unsigned long long ra[4], rb[4]; ulonglong2 xa[4], xb[4];
    ld16(r0, r1, r2, r3, xs, 0, RSTEP, ra, xa);
#pragma unroll 4
    for (int j = 0; j < 126; j += 2) {
        ld16(r0, r1, r2, r3, xs, j + 1, RSTEP, rb, xb);
        fb16(ra, xa, acc);
        ld16(r0, r1, r2, r3, xs, j + 2, RSTEP, ra, xa);
        fb16(rb, xb, acc);
    }
    ld16(r0, r1, r2, r3, xs, 127, RSTEP, rb, xb);
    fb16(ra, xa, acc);
    fb16(rb, xb, acc);
}

__device__ __forceinline__ void ld8(const float* r0, const float* r1, const float* r2, const float* r3,
                                    const float* xs, int j, int rstep,
                                    unsigned long long rr[4], ulonglong2 px[2]) {
    rr[0] = pack2(r0[j * rstep]);
    rr[1] = pack2(r1[j * rstep]);
    rr[2] = pack2(r2[j * rstep]);
    rr[3] = pack2(r3[j * rstep]);
    px[0] = *(const ulonglong2*)(xs + j * XSA);
    px[1] = *(const ulonglong2*)(xs + j * XSA + 4);
}
__device__ __forceinline__ void fb8(const unsigned long long rr[4], const ulonglong2 px[2],
                                    unsigned long long acc[16]) {
#pragma unroll
    for (int k = 0; k < 4; k++) {
        fma2(acc[k*4+0], rr[k], px[0].x); fma2(acc[k*4+1], rr[k], px[0].y);
        fma2(acc[k*4+2], rr[k], px[1].x); fma2(acc[k*4+3], rr[k], px[1].y);
    }
}

// TB=8 matvec, double-buffered.
template <int RSTEP>
__device__ __forceinline__ void matvec8(const float* __restrict__ r0, const float* __restrict__ r1,
                                        const float* __restrict__ r2, const float* __restrict__ r3,
                                        const float* __restrict__ xs, unsigned long long acc[16]) {
#pragma unroll
    for (int p = 0; p < 16; p++) acc[p] = 0ull;
    unsigned long long ra[4], rb[4]; ulonglong2 xa[2], xb[2];
    ld8(r0, r1, r2, r3, xs, 0, RSTEP, ra, xa);
#pragma unroll 4
    for (int j = 0; j < 126; j += 2) {
        ld8(r0, r1, r2, r3, xs, j + 1, RSTEP, rb, xb);
        fb8(ra, xa, acc);
        ld8(r0, r1, r2, r3, xs, j + 2, RSTEP, ra, xa);
        fb8(rb, xb, acc);
    }
    ld8(r0, r1, r2, r3, xs, 127, RSTEP, rb, xb);
    fb8(ra, xa, acc);
    fb8(rb, xb, acc);
}

__device__ __forceinline__ void stage_R(float* Rs, const float* __restrict__ R, int tid) {
#pragma unroll 4
    for (int idx = tid; idx < 128 * 128; idx += NTHREAD) {
        int i = idx >> 7, j = idx & 127;
        Rs[i * RSTRIDE + j] = R[idx];
    }
}

// ---------------- Phase 1: anchor head (ResidualQuant), TB=8, work-stealing ----------------
__global__ void __launch_bounds__(NTHREAD, 1)
anchor_kernel(const float* __restrict__ kv, const float* __restrict__ Ra,
              const float* __restrict__ cba, float* __restrict__ out, int ntask) {
    extern __shared__ float sm[];
    float* Rs = sm;
    const int tid = threadIdx.x;
    const int w = tid >> 5, L = tid & 31;
    float* xs = sm + 128 * RSTRIDE + w * WFA;

    stage_R(Rs, Ra, tid);
    const float c0 = cba[0], c1 = cba[1], c2 = cba[2], c3 = cba[3];
    const float t0 = 0.5f * (c0 + c1), t1 = 0.5f * (c1 + c2), t2 = 0.5f * (c2 + c3);
    __syncthreads();

    const float* rr0 = Rs + (L +  0) * RSTRIDE;
    const float* rr1 = Rs + (L + 32) * RSTRIDE;
    const float* rr2 = Rs + (L + 64) * RSTRIDE;
    const float* rr3 = Rs + (L + 96) * RSTRIDE;
    const float* rc0 = Rs + (L +  0);
    const float* rc1 = Rs + (L + 32);
    const float* rc2 = Rs + (L + 64);
    const float* rc3 = Rs + (L + 96);

    for (;;) {
        unsigned int task = next_task(0, L);
        if (task >= (unsigned)ntask) break;
        const int b = (int)(task >> 9);                 // 512 chunks per b
        const int sbase = ((int)task & 511) * TBA;
        const unsigned int base = ((unsigned)(b * HH) * SS + (unsigned)sbase) * DD;

        // ---- stage x (coalesced LDG.32, 4-way STS), batched reductions ----
        float sq[TBA], nn[TBA], inv[TBA];
#pragma unroll
        for (int t = 0; t < TBA; t++) {
            float ssq = 0.f;
#pragma unroll
            for (int c = 0; c < 4; c++) {
                int j = L + 32 * c;
                float x = kv[base + t * DD + j];
                xs[j * XSA + t] = x;
                ssq += x * x;
            }
            sq[t] = ssq;
        }
#pragma unroll
        for (int t = 0; t < TBA; t++) {
            float tot = warp_sum(sq[t]);
            nn[t] = sqrtf(tot);
            inv[t] = 1.0f / (nn[t] + EPSF);
        }
        __syncwarp();

        unsigned long long acc[16];
        matvec8<1>(rr0, rr1, rr2, rr3, xs, acc);

        // ---- pass A: quantize + |res| accumulation ----
        float A[TBA];
#pragma unroll
        for (int t = 0; t < TBA; t++) A[t] = 0.f;
#pragma unroll
        for (int k = 0; k < 4; k++) {
#pragma unroll
            for (int p = 0; p < 4; p++) {
                float2 y = unpack2(acc[k * 4 + p]);
                float y0 = y.x * inv[2 * p], y1 = y.y * inv[2 * p + 1];
                float q0 = (y0 <= t1) ? ((y0 <= t0) ? c0 : c1) : ((y0 <= t2) ? c2 : c3);
                float q1 = (y1 <= t1) ? ((y1 <= t0) ? c0 : c1) : ((y1 <= t2) ? c2 : c3);
                A[2 * p]     += fabsf(y0 - q0);
                A[2 * p + 1] += fabsf(y1 - q1);
            }
        }
#pragma unroll
        for (int t = 0; t < TBA; t++) A[t] = warp_sum(A[t]) * (1.0f / 128.0f);  // alpha

        __syncwarp();   // matvec1 done reading xs warp-wide

        // ---- pass B: yhat -> xs ----
#pragma unroll
        for (int k = 0; k < 4; k++) {
            int i = L + 32 * k;
#pragma unroll
            for (int p = 0; p < 4; p++) {
                float2 y = unpack2(acc[k * 4 + p]);
#pragma unroll
                for (int h = 0; h < 2; h++) {
                    int t = 2 * p + h;
                    float yy = (h ? y.y : y.x) * inv[t];
                    float q = (yy <= t1) ? ((yy <= t0) ? c0 : c1) : ((yy <= t2) ? c2 : c3);
                    float res = yy - q;
                    float sg = (res > 0.f) ? 1.f : ((res < 0.f) ? -1.f : 0.f);
                    xs[i * XSA + t] = q + A[t] * sg;
                }
            }
        }
        __syncwarp();

        matvec8<RSTRIDE>(rc0, rc1, rc2, rc3, xs, acc);

        // ---- output ----
#pragma unroll
        for (int t = 0; t < TBA; t++) {
            int p = t >> 1;
#pragma unroll
            for (int k = 0; k < 4; k++) {
                float2 r = unpack2(acc[k * 4 + p]);
                float rv = (t & 1) ? r.y : r.x;
                out[base + t * DD + L + 32 * k] = rv * nn[t];
            }
        }
        __syncwarp();
    }
}

// ---------------- Phase 2: delta heads (PolarQuant), TB=16, work-stealing ----------------
__global__ void __launch_bounds__(NTHREAD, 1)
delta_kernel(const float* __restrict__ kv, const float* __restrict__ Rd,
             const float* __restrict__ cbd, const float* __restrict__ anc,
             float* __restrict__ out, int ntask) {
    extern __shared__ float sm[];
    float* Rs = sm;
    const int tid = threadIdx.x;
    const int w = tid >> 5, L = tid & 31;
    float* xs = sm + 128 * RSTRIDE + w * WFD;
    float* st = xs + 128 * XSD;      // stash: st[t] = nn, st[16+t] = inv

    stage_R(Rs, Rd, tid);
    const float c0 = cbd[0], c1 = cbd[1];
    const float mid = 0.5f * (c0 + c1);
    __syncthreads();

    const float* rr0 = Rs + (L +  0) * RSTRIDE;
    const float* rr1 = Rs + (L + 32) * RSTRIDE;
    const float* rr2 = Rs + (L + 64) * RSTRIDE;
    const float* rr3 = Rs + (L + 96) * RSTRIDE;
    const float* rc0 = Rs + (L +  0);
    const float* rc1 = Rs + (L + 32);
    const float* rc2 = Rs + (L + 64);
    const float* rc3 = Rs + (L + 96);

    for (;;) {
        unsigned int task = next_task(1, L);
        if (task >= (unsigned)ntask) break;
        // head-minor: consecutive tasks = same chunk, different head (anchor chunk L2 reuse)
        const int chunk = (int)(task / 7);
        const int h = (int)(task - chunk * 7) + 1;
        const int b = chunk >> 8;                       // 256 chunks per b
        const int sbase = (chunk & 255) * TBD;
        const unsigned int kbase = ((unsigned)(b * HH + h) * SS + (unsigned)sbase) * DD;
        const unsigned int abase = ((unsigned)(b * HH) * SS + (unsigned)sbase) * DD;

        // ---- stage delta = kv - anchor in two 8-token halves (low reg pressure),
        //      reductions batched per half, nn/inv stashed to smem ----
#pragma unroll
        for (int half = 0; half < 2; half++) {
            float sq[8];
#pragma unroll
            for (int u = 0; u < 8; u++) {
                int t = half * 8 + u;
                float ssq = 0.f;
#pragma unroll
                for (int c = 0; c < 4; c++) {
                    int j = L + 32 * c;
                    float x = kv[kbase + t * DD + j] - anc[abase + t * DD + j];
                    xs[j * XSD + t] = x;
                    ssq += x * x;
                }
                sq[u] = ssq;
            }
#pragma unroll
            for (int u = 0; u < 8; u++) {
                int t = half * 8 + u;
                float tot = warp_sum(sq[u]);
                if (L == t) {                       // lane t owns token t's stash
                    float nn = sqrtf(tot);
                    st[t] = nn;
                    st[16 + t] = 1.0f / (nn + EPSF);
                }
            }
        }
        __syncwarp();

        unsigned long long acc[32];
        matvec16<1>(rr0, rr1, rr2, rr3, xs, acc);

        __syncwarp();   // all lanes done reading xs

        // ---- 1-bit polar quantize -> xs (inv via LDS broadcast) ----
#pragma unroll
        for (int p = 0; p < 8; p++) {
            float i0 = st[16 + 2 * p], i1 = st[16 + 2 * p + 1];
#pragma unroll
            for (int k = 0; k < 4; k++) {
                int i = L + 32 * k;
                float2 y = unpack2(acc[k * 8 + p]);
                float y0 = y.x * i0, y1 = y.y * i1;
                xs[i * XSD + 2 * p]     = (y0 <= mid) ? c0 : c1;
                xs[i * XSD + 2 * p + 1] = (y1 <= mid) ? c0 : c1;
            }
        }
        __syncwarp();

        matvec16<RSTRIDE>(rc0, rc1, rc2, rc3, xs, acc);

        // ---- output: out = anchor + rec * norm (nn via LDS broadcast) ----
#pragma unroll
        for (int t = 0; t < TBD; t++) {
            int p = t >> 1;
            float nn = st[t];
#pragma unroll
            for (int k = 0; k < 4; k++) {
                float2 r = unpack2(acc[k * 8 + p]);
                float rv = (t & 1) ? r.y : r.x;
                int j = L + 32 * k;
                out[kbase + t * DD + j] = anc[abase + t * DD + j] + rv * nn;
            }
        }
        __syncwarp();
    }
}

extern "C" void kernel_launch(void* const* d_in, const int* in_sizes, int n_in,
                              void* d_out, int out_size) {
    const float* kv  = (const float*)d_in[0];
    const float* Ra  = (const float*)d_in[1];
    const float* cba = (const float*)d_in[2];
    const float* Rd  = (const float*)d_in[3];
    const float* cbd = (const float*)d_in[4];
    float* out = (float*)d_out;

    const int smem_a = SMEM_FLOATS_A * (int)sizeof(float);  // 139776
    const int smem_d = SMEM_FLOATS_D * (int)sizeof(float);  // 190464
    cudaFuncSetAttribute(anchor_kernel, cudaFuncAttributeMaxDynamicSharedMemorySize, smem_a);
    cudaFuncSetAttribute(delta_kernel,  cudaFuncAttributeMaxDynamicSharedMemorySize, smem_d);

    // Reset work-stealing counters via a memset node (graph-capturable).
    static void* ctr_addr = nullptr;
    if (!ctr_addr) cudaGetSymbolAddress(&ctr_addr, g_ctr);
    cudaMemsetAsync(ctr_addr, 0, 2 * sizeof(unsigned int));

    const int n_anchor_task = (BB * SS) / TBA;            // 4096
    const int n_delta_task  = (BB * SS) / TBD * 7;        // 14336

    anchor_kernel<<<NBLOCK, NTHREAD, smem_a>>>(kv, Ra, cba, out, n_anchor_task);
    delta_kernel <<<NBLOCK, NTHREAD, smem_d>>>(kv, Rd, cbd, out, out, n_delta_task);
}

// round 16
// speedup vs baseline: 1.1169x; 1.0045x over previous
#include <cuda_runtime.h>
#include <math.h>

// Problem constants (fixed by the reference).
#define DD   128
#define HH   8
#define BB   8
#define SS   4096
#define EPSF 1e-8f
#define TBA  8            // tokens per anchor task
#define TBD  16           // tokens per delta task
#define RSTRIDE 129       // padded R row stride: conflict-free row & column scalar reads
#define XSA  12           // anchor xs row stride (16B-aligned rows)
#define XSD  20           // delta xs row stride (16B-aligned rows)
#define NTHREAD 384       // 12 warps/SM, ~170-reg budget
#define NWARP   12
#define NBLOCK  148

// Per-warp smem floats: delta = xs(128*20) + stash(32); anchor = xs(128*12)
#define WFD (128*XSD + 32)
#define WFA (128*XSA)
#define SMEM_FLOATS_A (128*RSTRIDE + NWARP*WFA)   // 34944  -> 139776 B
#define SMEM_FLOATS_D (128*RSTRIDE + NWARP*WFD)   // 47616  -> 190464 B

// Work-stealing counters; zeroed by cudaMemsetAsync before each replay.
__device__ unsigned int g_ctr[2];

// ---------------- Blackwell packed-fp32 helpers ----------------
__device__ __forceinline__ unsigned long long pack2(float x) {
    unsigned long long d; unsigned int u = __float_as_uint(x);
    asm("mov.b64 %0, {%1, %1};" : "=l"(d) : "r"(u));
    return d;
}
__device__ __forceinline__ void fma2(unsigned long long& d, unsigned long long a, unsigned long long b) {
    asm("fma.rn.f32x2 %0, %1, %2, %0;" : "+l"(d) : "l"(a), "l"(b));
}
__device__ __forceinline__ float2 unpack2(unsigned long long p) {
    unsigned int lo, hi;
    asm("mov.b64 {%0, %1}, %2;" : "=r"(lo), "=r"(hi) : "l"(p));
    return make_float2(__uint_as_float(lo), __uint_as_float(hi));
}
__device__ __forceinline__ float warp_sum(float v) {
#pragma unroll
    for (int o = 16; o; o >>= 1) v += __shfl_xor_sync(0xffffffffu, v, o);
    return v;
}
__device__ __forceinline__ unsigned int next_task(int which, int lane) {
    unsigned int t;
    if (lane == 0) t = atomicAdd(&g_ctr[which], 1u);
    return __shfl_sync(0xffffffffu, t, 0);
}

// ---------------- software-pipelined matvecs (validated in R15) ----------------

__device__ __forceinline__ void ld16(const float* r0, const float* r1, const float* r2, const float* r3,
                                     const float* xs, int j, int rstep,
                                     unsigned long long rr[4], ulonglong2 px[4]) {
    rr[0] = pack2(r0[j * rstep]);
    rr[1] = pack2(r1[j * rstep]);
    rr[2] = pack2(r2[j * rstep]);
    rr[3] = pack2(r3[j * rstep]);
    px[0] = *(const ulonglong2*)(xs + j * XSD);
    px[1] = *(const ulonglong2*)(xs + j * XSD + 4);
    px[2] = *(const ulonglong2*)(xs + j * XSD + 8);
    px[3] = *(const ulonglong2*)(xs + j * XSD + 12);
}
__device__ __forceinline__ void fb16(const unsigned long long rr[4], const ulonglong2 px[4],
                                     unsigned long long acc[32]) {
#pragma unroll
    for (int k = 0; k < 4; k++) {
        fma2(acc[k*8+0], rr[k], px[0].x); fma2(acc[k*8+1], rr[k], px[0].y);
        fma2(acc[k*8+2], rr[k], px[1].x); fma2(acc[k*8+3], rr[k], px[1].y);
        fma2(acc[k*8+4], rr[k], px[2].x); fma2(acc[k*8+5], rr[k], px[2].y);
        fma2(acc[k*8+6], rr[k], px[3].x); fma2(acc[k*8+7], rr[k], px[3].y);
    }
}

template <int RSTEP>
__device__ __forceinline__ void matvec16(const float* __restrict__ r0, const float* __restrict__ r1,
                                         const float* __restrict__ r2, const float* __restrict__ r3,
                                         const float* __restrict__ xs, unsigned long long acc[32]) {
#pragma unroll
    for (int p = 0; p < 32; p++) acc[p] = 0ull;
    unsigned long long ra[4], rb[4]; ulonglong2 xa[4], xb[4];
    ld16(r0, r1, r2, r3, xs, 0, RSTEP, ra, xa);
#pragma unroll 4
    for (int j = 0; j < 126; j += 2) {
        ld16(r0, r1, r2, r3, xs, j + 1, RSTEP, rb, xb);
        fb16(ra, xa, acc);
        ld16(r0, r1, r2, r3, xs, j + 2, RSTEP, ra, xa);
        fb16(rb, xb, acc);
    }
    ld16(r0, r1, r2, r3, xs, 127, RSTEP, rb, xb);
    fb16(ra, xa, acc);
    fb16(rb, xb, acc);
}

__device__ __forceinline__ void ld8(const float* r0, const float* r1, const float* r2, const float* r3,
                                    const float* xs, int j, int rstep,
                                    unsigned long long rr[4], ulonglong2 px[2]) {
    rr[0] = pack2(r0[j * rstep]);
    rr[1] = pack2(r1[j * rstep]);
    rr[2] = pack2(r2[j * rstep]);
    rr[3] = pack2(r3[j * rstep]);
    px[0] = *(const ulonglong2*)(xs + j * XSA);
    px[1] = *(const ulonglong2*)(xs + j * XSA + 4);
}
__device__ __forceinline__ void fb8(const unsigned long long rr[4], const ulonglong2 px[2],
                                    unsigned long long acc[16]) {
#pragma unroll
    for (int k = 0; k < 4; k++) {
        fma2(acc[k*4+0], rr[k], px[0].x); fma2(acc[k*4+1], rr[k], px[0].y);
        fma2(acc[k*4+2], rr[k], px[1].x); fma2(acc[k*4+3], rr[k], px[1].y);
    }
}

template <int RSTEP>
__device__ __forceinline__ void matvec8(const float* __restrict__ r0, const float* __restrict__ r1,
                                        const float* __restrict__ r2, const float* __restrict__ r3,
                                        const float* __restrict__ xs, unsigned long long acc[16]) {
#pragma unroll
    for (int p = 0; p < 16; p++) acc[p] = 0ull;
    unsigned long long ra[4], rb[4]; ulonglong2 xa[2], xb[2];
    ld8(r0, r1, r2, r3, xs, 0, RSTEP, ra, xa);
#pragma unroll 4
    for (int j = 0; j < 126; j += 2) {
        ld8(r0, r1, r2, r3, xs, j + 1, RSTEP, rb, xb);
        fb8(ra, xa, acc);
        ld8(r0, r1, r2, r3, xs, j + 2, RSTEP, ra, xa);
        fb8(rb, xb, acc);
    }
    ld8(r0, r1, r2, r3, xs, 127, RSTEP, rb, xb);
    fb8(ra, xa, acc);
    fb8(rb, xb, acc);
}

__device__ __forceinline__ void stage_R(float* Rs, const float* __restrict__ R, int tid) {
#pragma unroll 4
    for (int idx = tid; idx < 128 * 128; idx += NTHREAD) {
        int i = idx >> 7, j = idx & 127;
        Rs[i * RSTRIDE + j] = R[idx];
    }
}

// ---------------- Phase 1: anchor head (ResidualQuant), TB=8, work-stealing ----------------
__global__ void __launch_bounds__(NTHREAD, 1)
anchor_kernel(const float* __restrict__ kv, const float* __restrict__ Ra,
              const float* __restrict__ cba, float* __restrict__ out, int ntask) {
    extern __shared__ float sm[];
    float* Rs = sm;
    const int tid = threadIdx.x;
    const int w = tid >> 5, L = tid & 31;
    float* xs = sm + 128 * RSTRIDE + w * WFA;

    stage_R(Rs, Ra, tid);
    const float c0 = cba[0], c1 = cba[1], c2 = cba[2], c3 = cba[3];
    const float t0 = 0.5f * (c0 + c1), t1 = 0.5f * (c1 + c2), t2 = 0.5f * (c2 + c3);
    __syncthreads();

    const float* rr0 = Rs + (L +  0) * RSTRIDE;
    const float* rr1 = Rs + (L + 32) * RSTRIDE;
    const float* rr2 = Rs + (L + 64) * RSTRIDE;
    const float* rr3 = Rs + (L + 96) * RSTRIDE;
    const float* rc0 = Rs + (L +  0);
    const float* rc1 = Rs + (L + 32);
    const float* rc2 = Rs + (L + 64);
    const float* rc3 = Rs + (L + 96);

    for (;;) {
        unsigned int task = next_task(0, L);
        if (task >= (unsigned)ntask) break;
        const int b = (int)(task >> 9);                 // 512 chunks per b
        const int sbase = ((int)task & 511) * TBA;
        const unsigned int base = ((unsigned)(b * HH) * SS + (unsigned)sbase) * DD;

        // ---- stage x with rotating 1-token prefetch; reductions in one batch ----
        float sq[TBA], nn[TBA], inv[TBA];
        {
            float ka[4], kb[4];
#pragma unroll
            for (int c = 0; c < 4; c++) ka[c] = kv[base + 0 * DD + L + 32 * c];
#pragma unroll
            for (int t = 0; t < TBA; t++) {
                if (t < TBA - 1) {
#pragma unroll
                    for (int c = 0; c < 4; c++) kb[c] = kv[base + (t + 1) * DD + L + 32 * c];
                }
                float ssq = 0.f;
#pragma unroll
                for (int c = 0; c < 4; c++) {
                    float x = ka[c];
                    xs[(L + 32 * c) * XSA + t] = x;
                    ssq += x * x;
                }
                sq[t] = ssq;
#pragma unroll
                for (int c = 0; c < 4; c++) ka[c] = kb[c];
            }
        }
#pragma unroll
        for (int t = 0; t < TBA; t++) {
            float tot = warp_sum(sq[t]);
            nn[t] = sqrtf(tot);
            inv[t] = 1.0f / (nn[t] + EPSF);
        }
        __syncwarp();

        unsigned long long acc[16];
        matvec8<1>(rr0, rr1, rr2, rr3, xs, acc);

        // ---- pass A: quantize + |res| accumulation ----
        float A[TBA];
#pragma unroll
        for (int t = 0; t < TBA; t++) A[t] = 0.f;
#pragma unroll
        for (int k = 0; k < 4; k++) {
#pragma unroll
            for (int p = 0; p < 4; p++) {
                float2 y = unpack2(acc[k * 4 + p]);
                float y0 = y.x * inv[2 * p], y1 = y.y * inv[2 * p + 1];
                float q0 = (y0 <= t1) ? ((y0 <= t0) ? c0 : c1) : ((y0 <= t2) ? c2 : c3);
                float q1 = (y1 <= t1) ? ((y1 <= t0) ? c0 : c1) : ((y1 <= t2) ? c2 : c3);
                A[2 * p]     += fabsf(y0 - q0);
                A[2 * p + 1] += fabsf(y1 - q1);
            }
        }
#pragma unroll
        for (int t = 0; t < TBA; t++) A[t] = warp_sum(A[t]) * (1.0f / 128.0f);  // alpha

        __syncwarp();   // matvec1 done reading xs warp-wide

        // ---- pass B: yhat -> xs ----
#pragma unroll
        for (int k = 0; k < 4; k++) {
            int i = L + 32 * k;
#pragma unroll
            for (int p = 0; p < 4; p++) {
                float2 y = unpack2(acc[k * 4 + p]);
#pragma unroll
                for (int h = 0; h < 2; h++) {
                    int t = 2 * p + h;
                    float yy = (h ? y.y : y.x) * inv[t];
                    float q = (yy <= t1) ? ((yy <= t0) ? c0 : c1) : ((yy <= t2) ? c2 : c3);
                    float res = yy - q;
                    float sg = (res > 0.f) ? 1.f : ((res < 0.f) ? -1.f : 0.f);
                    xs[i * XSA + t] = q + A[t] * sg;
                }
            }
        }
        __syncwarp();

        matvec8<RSTRIDE>(rc0, rc1, rc2, rc3, xs, acc);

        // ---- output ----
#pragma unroll
        for (int t = 0; t < TBA; t++) {
            int p = t >> 1;
#pragma unroll
            for (int k = 0; k < 4; k++) {
                float2 r = unpack2(acc[k * 4 + p]);
                float rv = (t & 1) ? r.y : r.x;
                out[base + t * DD + L + 32 * k] = rv * nn[t];
            }
        }
        __syncwarp();
    }
}

// ---------------- Phase 2: delta heads (PolarQuant), TB=16, work-stealing ----------------
__global__ void __launch_bounds__(NTHREAD, 1)
delta_kernel(const float* __restrict__ kv, const float* __restrict__ Rd,
             const float* __restrict__ cbd, const float* __restrict__ anc,
             float* __restrict__ out, int ntask) {
    extern __shared__ float sm[];
    float* Rs = sm;
    const int tid = threadIdx.x;
    const int w = tid >> 5, L = tid & 31;
    float* xs = sm + 128 * RSTRIDE + w * WFD;
    float* st = xs + 128 * XSD;      // stash: st[t] = nn, st[16+t] = inv

    stage_R(Rs, Rd, tid);
    const float c0 = cbd[0], c1 = cbd[1];
    const float mid = 0.5f * (c0 + c1);
    __syncthreads();

    const float* rr0 = Rs + (L +  0) * RSTRIDE;
    const float* rr1 = Rs + (L + 32) * RSTRIDE;
    const float* rr2 = Rs + (L + 64) * RSTRIDE;
    const float* rr3 = Rs + (L + 96) * RSTRIDE;
    const float* rc0 = Rs + (L +  0);
    const float* rc1 = Rs + (L + 32);
    const float* rc2 = Rs + (L + 64);
    const float* rc3 = Rs + (L + 96);

    for (;;) {
        unsigned int task = next_task(1, L);
        if (task >= (unsigned)ntask) break;
        // head-minor: consecutive tasks = same chunk, different head (anchor chunk L2 reuse)
        const int chunk = (int)(task / 7);
        const int h = (int)(task - chunk * 7) + 1;
        const int b = chunk >> 8;                       // 256 chunks per b
        const int sbase = (chunk & 255) * TBD;
        const unsigned int kbase = ((unsigned)(b * HH + h) * SS + (unsigned)sbase) * DD;
        const unsigned int abase = ((unsigned)(b * HH) * SS + (unsigned)sbase) * DD;

        // ---- stage delta = kv - anchor with rotating 1-token prefetch;
        //      single batch of 16 shfl trees; nn/inv stashed to smem ----
        {
            float sq[TBD];
            float ka[4], aa[4], kb[4], ab[4];
#pragma unroll
            for (int c = 0; c < 4; c++) {
                ka[c] = kv[kbase + 0 * DD + L + 32 * c];
                aa[c] = anc[abase + 0 * DD + L + 32 * c];
            }
#pragma unroll
            for (int t = 0; t < TBD; t++) {
                if (t < TBD - 1) {
#pragma unroll
                    for (int c = 0; c < 4; c++) {
                        kb[c] = kv[kbase + (t + 1) * DD + L + 32 * c];
                        ab[c] = anc[abase + (t + 1) * DD + L + 32 * c];
                    }
                }
                float ssq = 0.f;
#pragma unroll
                for (int c = 0; c < 4; c++) {
                    float x = ka[c] - aa[c];
                    xs[(L + 32 * c) * XSD + t] = x;
                    ssq += x * x;
                }
                sq[t] = ssq;
#pragma unroll
                for (int c = 0; c < 4; c++) { ka[c] = kb[c]; aa[c] = ab[c]; }
            }
#pragma unroll
            for (int t = 0; t < TBD; t++) {
                float tot = warp_sum(sq[t]);
                if (L == t) {                       // lane t owns token t's stash
                    float nn = sqrtf(tot);
                    st[t] = nn;
                    st[16 + t] = 1.0f / (nn + EPSF);
                }
            }
        }
        __syncwarp();

        unsigned long long acc[32];
        matvec16<1>(rr0, rr1, rr2, rr3, xs, acc);

        __syncwarp();   // all lanes done reading xs

        // ---- 1-bit polar quantize -> xs (inv via LDS broadcast) ----
#pragma unroll
        for (int p = 0; p < 8; p++) {
            float i0 = st[16 + 2 * p], i1 = st[16 + 2 * p + 1];
#pragma unroll
            for (int k = 0; k < 4; k++) {
                int i = L + 32 * k;
                float2 y = unpack2(acc[k * 8 + p]);
                float y0 = y.x * i0, y1 = y.y * i1;
                xs[i * XSD + 2 * p]     = (y0 <= mid) ? c0 : c1;
                xs[i * XSD + 2 * p + 1] = (y1 <= mid) ? c0 : c1;
            }
        }
        __syncwarp();

        matvec16<RSTRIDE>(rc0, rc1, rc2, rc3, xs, acc);

        // ---- output: out = anchor + rec * norm (nn via LDS broadcast; anchor L1-hot) ----
#pragma unroll
        for (int t = 0; t < TBD; t++) {
            int p = t >> 1;
            float nn = st[t];
#pragma unroll
            for (int k = 0; k < 4; k++) {
                float2 r = unpack2(acc[k * 8 + p]);
                float rv = (t & 1) ? r.y : r.x;
                int j = L + 32 * k;
                out[kbase + t * DD + j] = anc[abase + t * DD + j] + rv * nn;
            }
        }
        __syncwarp();
    }
}

extern "C" void kernel_launch(void* const* d_in, const int* in_sizes, int n_in,
                              void* d_out, int out_size) {
    const float* kv  = (const float*)d_in[0];
    const float* Ra  = (const float*)d_in[1];
    const float* cba = (const float*)d_in[2];
    const float* Rd  = (const float*)d_in[3];
    const float* cbd = (const float*)d_in[4];
    float* out = (float*)d_out;

    const int smem_a = SMEM_FLOATS_A * (int)sizeof(float);  // 139776
    const int smem_d = SMEM_FLOATS_D * (int)sizeof(float);  // 190464
    cudaFuncSetAttribute(anchor_kernel, cudaFuncAttributeMaxDynamicSharedMemorySize, smem_a);
    cudaFuncSetAttribute(delta_kernel,  cudaFuncAttributeMaxDynamicSharedMemorySize, smem_d);

    // Reset work-stealing counters via a memset node (graph-capturable).
    static void* ctr_addr = nullptr;
    if (!ctr_addr) cudaGetSymbolAddress(&ctr_addr, g_ctr);
    cudaMemsetAsync(ctr_addr, 0, 2 * sizeof(unsigned int));

    const int n_anchor_task = (BB * SS) / TBA;            // 4096
    const int n_delta_task  = (BB * SS) / TBD * 7;        // 14336

    anchor_kernel<<<NBLOCK, NTHREAD, smem_a>>>(kv, Ra, cba, out, n_anchor_task);
    delta_kernel <<<NBLOCK, NTHREAD, smem_d>>>(kv, Rd, cbd, out, out, n_delta_task);
}